// round 9
// baseline (speedup 1.0000x reference)
#include <cuda_runtime.h>
#include <math.h>

typedef unsigned long long ull;

#define BB   8192
#define VV   100000
#define ND   15
#define SL   50
#define HID  30
#define NSPLIT 8
#define KSPL 144            /* k per split: 8*144 = 1152 */
#define KC   48             /* k per smem stage */
#define TSTR 52             /* smem tile stride (208 B ≡ 80 mod 128, odd*16 -> conflict-free) */

// X scratch: [row][0..1023 features | 1024..1143 lp | 1144..1151 zero]
__device__ float g_X[(size_t)BB * 1152];
// W1 n-major: g_W1NK[n][k], n<32 (rows 30,31 zero), k<1152 (tail zero)
__device__ float g_W1NK[32 * 1152];
// split-K partials: [split][row][n(32)]
__device__ float g_P[NSPLIT * BB * 32];

// ---------------- f32x2 helpers ----------------
__device__ __forceinline__ ull f2_pack(float x, float y) {
    ull r; asm("mov.b64 %0, {%1, %2};" : "=l"(r) : "f"(x), "f"(y)); return r;
}
__device__ __forceinline__ ull f2_mul(ull a, ull b) {
    ull r; asm("mul.rn.f32x2 %0, %1, %2;" : "=l"(r) : "l"(a), "l"(b)); return r;
}
__device__ __forceinline__ ull f2_add(ull a, ull b) {
    ull r; asm("add.rn.f32x2 %0, %1, %2;" : "=l"(r) : "l"(a), "l"(b)); return r;
}
__device__ __forceinline__ void f2_fma(ull& d, ull a, ull b) {
    asm("fma.rn.f32x2 %0, %1, %2, %0;" : "+l"(d) : "l"(a), "l"(b));
}
__device__ __forceinline__ float f2_hadd(ull a) {
    float lo, hi; asm("mov.b64 {%0, %1}, %2;" : "=f"(lo), "=f"(hi) : "l"(a));
    return lo + hi;
}

// ---------------- K1: gather + fused pairwise (warp-autonomous) + W prep ----------------
__global__ __launch_bounds__(256) void gather_kernel(
    const int*   __restrict__ dense_ids,
    const int*   __restrict__ seq_ids,
    const float* __restrict__ tables_dense,
    const float* __restrict__ table_seq,
    const float* __restrict__ inner_w,
    const float* __restrict__ W1)
{
    if (blockIdx.x >= BB / 8) {
        // prep: W1 [1144x30] -> g_W1NK [32x1152] n-major, zero-padded
        int base = (blockIdx.x - BB / 8) * 256 + threadIdx.x;
        for (int e = base; e < 32 * 1152; e += 9 * 256) {
            int n = e / 1152;
            int k = e - n * 1152;
            g_W1NK[e] = (n < HID && k < 1144) ? W1[k * HID + n] : 0.0f;
        }
        return;
    }

    __shared__ float Xs[8 * 1028];

    const int l   = threadIdx.x & 31;
    const int w   = threadIdx.x >> 5;
    const int row = blockIdx.x * 8 + w;

    // dense gather (random, DRAM; 15 loads in flight)
    ull e[16];
    const ull* td = (const ull*)tables_dense;
    const int* dr = dense_ids + row * ND;
    #pragma unroll
    for (int f = 0; f < ND; f++) {
        int id = __ldg(dr + f);
        e[f] = __ldg(td + ((size_t)f * VV + (size_t)id) * 32 + l);
    }

    // sequence mean (L2-resident), dual accumulators
    const int* sr = seq_ids + row * SL;
    const ull* ts = (const ull*)table_seq;
    ull acc0 = 0, acc1 = 0;
    #pragma unroll 10
    for (int s = 0; s < SL; s += 2) {
        int id0 = __ldg(sr + s);
        int id1 = __ldg(sr + s + 1);
        acc0 = f2_add(acc0, __ldg(ts + (size_t)id0 * 32 + l));
        acc1 = f2_add(acc1, __ldg(ts + (size_t)id1 * 32 + l));
    }
    e[15] = f2_mul(f2_add(acc0, acc1), f2_pack(1.0f / 50.0f, 1.0f / 50.0f));

    // store features: own smem slice (pairwise input) + global X row
    ull* Xw  = (ull*)(Xs + w * 1028);
    ull* Xg  = (ull*)(g_X + (size_t)row * 1152);
    #pragma unroll
    for (int f = 0; f < 16; f++) {
        Xw[f * 32 + l] = e[f];
        Xg[f * 32 + l] = e[f];
    }
    if (l < 8) g_X[(size_t)row * 1152 + 1144 + l] = 0.0f;    // zero pad
    __syncwarp();

    // pairwise: lane s -> pairs s, s+32, s+64, s+96
    const float* Xr = Xs + w * 1028;
    const int s = l;
    #pragma unroll
    for (int t = 0; t < 4; t++) {
        int p = s + 32 * t;
        if (p >= 120) break;
        int a = 0, rem = p, cnt = 15;
        while (rem >= cnt) { rem -= cnt; cnt--; a++; }
        int b = a + 1 + rem;
        const float* pa = Xr + a * 64;
        const float* pb = Xr + b * 64;
        const float* pw = inner_w + p * 64;
        ull d = 0;
        #pragma unroll
        for (int ii = 0; ii < 16; ii++) {
            int i = (s + ii) & 15;                 // lane rotation: conflict-reduced LDS
            ulonglong2 xa = *(const ulonglong2*)(pa + i * 4);
            ulonglong2 xb = *(const ulonglong2*)(pb + i * 4);
            ulonglong2 wv = __ldg((const ulonglong2*)(pw + i * 4));
            f2_fma(d, f2_mul(xa.x, xb.x), wv.x);
            f2_fma(d, f2_mul(xa.y, xb.y), wv.y);
        }
        g_X[(size_t)row * 1152 + 1024 + p] = f2_hadd(d);
    }
}

// ---------------- K2: split-K GEMM. block = 64 rows x 32 cols x 144 k ----------------
__global__ __launch_bounds__(128) void mlp_kernel()
{
    __shared__ float Xsh[64 * TSTR];
    __shared__ float Wsh[32 * TSTR];

    const int t    = threadIdx.x;
    const int spl  = blockIdx.x & 7;
    const int tile = blockIdx.x >> 3;
    const int row0 = tile * 64;
    const int k0s  = spl * KSPL;

    const int cc = t & 7;          // cols cc + 8h, h = 0..3
    const int rr = t >> 3;         // rows 4rr .. 4rr+3

    ull acc[4][4];
    #pragma unroll
    for (int i = 0; i < 4; i++)
        #pragma unroll
        for (int h = 0; h < 4; h++) acc[i][h] = 0;

    for (int c = 0; c < KSPL / KC; c++) {
        const int k0 = k0s + c * KC;
        // stage X: 64 rows x 48 k. thread: row t>>1, 24 floats at (t&1)*24
        {
            int m  = t >> 1;
            int kk = (t & 1) * 24;
            const float4* src = (const float4*)(g_X + (size_t)(row0 + m) * 1152 + k0 + kk);
            float4* dst = (float4*)(Xsh + m * TSTR + kk);
            #pragma unroll
            for (int j = 0; j < 6; j++) dst[j] = __ldg(src + j);
        }
        // stage W: 32 n x 48 k. thread: n = t>>2, 12 floats at (t&3)*12
        {
            int n  = t >> 2;
            int kk = (t & 3) * 12;
            const float4* src = (const float4*)(g_W1NK + n * 1152 + k0 + kk);
            float4* dst = (float4*)(Wsh + n * TSTR + kk);
            #pragma unroll
            for (int j = 0; j < 3; j++) dst[j] = __ldg(src + j);
        }
        __syncthreads();

        #pragma unroll
        for (int k4 = 0; k4 < KC / 4; k4++) {
            ulonglong2 wv[4];
            #pragma unroll
            for (int h = 0; h < 4; h++)
                wv[h] = *(const ulonglong2*)(Wsh + (cc + 8 * h) * TSTR + k4 * 4);
            #pragma unroll
            for (int i = 0; i < 4; i++) {
                ulonglong2 x = *(const ulonglong2*)(Xsh + (4 * rr + i) * TSTR + k4 * 4);
                #pragma unroll
                for (int h = 0; h < 4; h++) {
                    f2_fma(acc[i][h], x.x, wv[h].x);
                    f2_fma(acc[i][h], x.y, wv[h].y);
                }
            }
        }
        __syncthreads();
    }

    // write partials (deterministic, coalesced within warp quads)
    float* P = g_P + ((size_t)spl * BB + row0) * 32;
    #pragma unroll
    for (int i = 0; i < 4; i++)
        #pragma unroll
        for (int h = 0; h < 4; h++)
            P[(4 * rr + i) * 32 + cc + 8 * h] = f2_hadd(acc[i][h]);
}

// ---------------- K3: head — reduce splits, relu, W2, sigmoid ----------------
__global__ __launch_bounds__(256) void head_kernel(
    const float* __restrict__ b1,
    const float* __restrict__ W2,
    const float* __restrict__ b2,
    float*       __restrict__ out)
{
    const int row = blockIdx.x * 256 + threadIdx.x;
    float4 h[8];
    #pragma unroll
    for (int j = 0; j < 8; j++) h[j] = make_float4(0.f, 0.f, 0.f, 0.f);
    #pragma unroll
    for (int s = 0; s < NSPLIT; s++) {
        const float4* P = (const float4*)(g_P + ((size_t)s * BB + row) * 32);
        #pragma unroll
        for (int j = 0; j < 8; j++) {
            float4 v = __ldg(P + j);
            h[j].x += v.x; h[j].y += v.y; h[j].z += v.z; h[j].w += v.w;
        }
    }
    const float* hf = (const float*)h;
    float z = 0.f;
    #pragma unroll
    for (int n = 0; n < HID; n++)
        z += fmaxf(hf[n] + __ldg(b1 + n), 0.f) * __ldg(W2 + n);
    z += __ldg(b2);
    out[row] = 1.0f / (1.0f + expf(-z));
}

extern "C" void kernel_launch(void* const* d_in, const int* in_sizes, int n_in,
                              void* d_out, int out_size) {
    const int*   dense_ids    = (const int*)  d_in[0];
    const int*   seq_ids      = (const int*)  d_in[1];
    const float* tables_dense = (const float*)d_in[2];
    const float* table_seq    = (const float*)d_in[3];
    const float* inner_w      = (const float*)d_in[4];
    const float* W1           = (const float*)d_in[5];
    const float* b1           = (const float*)d_in[6];
    const float* W2           = (const float*)d_in[7];
    const float* b2           = (const float*)d_in[8];
    float* out = (float*)d_out;
    (void)in_sizes; (void)n_in; (void)out_size;

    gather_kernel<<<BB / 8 + 9, 256>>>(dense_ids, seq_ids, tables_dense,
                                       table_seq, inner_w, W1);
    mlp_kernel<<<(BB / 64) * NSPLIT, 128>>>();
    head_kernel<<<BB / 256, 256>>>(b1, W2, b2, out);
}

// round 10
// speedup vs baseline: 1.2444x; 1.2444x over previous
#include <cuda_runtime.h>
#include <math.h>

typedef unsigned long long ull;

#define BB   8192
#define VV   100000
#define ND   15
#define SL   50
#define HID  30
#define NSPLIT 8
#define KSPL 144            /* k per split: 8*144 = 1152 */
#define KC   48             /* k per smem stage */
#define TSTR 52             /* smem tile stride (208 B) */

// X scratch: [row][0..1023 features | 1024..1143 lp | 1144..1151 zero]
__device__ float g_X[(size_t)BB * 1152];
// W1 n-major: g_W1NK[n][k], n<32 (rows 30,31 zero), k<1152 (tail zero)
__device__ float g_W1NK[32 * 1152];
// split-K partials: [split][row][n(32)]
__device__ float g_P[NSPLIT * BB * 32];

// ---------------- f32x2 helpers ----------------
__device__ __forceinline__ ull f2_pack(float x, float y) {
    ull r; asm("mov.b64 %0, {%1, %2};" : "=l"(r) : "f"(x), "f"(y)); return r;
}
__device__ __forceinline__ ull f2_mul(ull a, ull b) {
    ull r; asm("mul.rn.f32x2 %0, %1, %2;" : "=l"(r) : "l"(a), "l"(b)); return r;
}
__device__ __forceinline__ ull f2_add(ull a, ull b) {
    ull r; asm("add.rn.f32x2 %0, %1, %2;" : "=l"(r) : "l"(a), "l"(b)); return r;
}
__device__ __forceinline__ void f2_fma(ull& d, ull a, ull b) {
    asm("fma.rn.f32x2 %0, %1, %2, %0;" : "+l"(d) : "l"(a), "l"(b));
}
__device__ __forceinline__ float f2_hadd(ull a) {
    float lo, hi; asm("mov.b64 {%0, %1}, %2;" : "=f"(lo), "=f"(hi) : "l"(a));
    return lo + hi;
}

// ---------------- K1: gather + register pairwise (smem-transpose reduce) ----------------
__global__ __launch_bounds__(256, 4) void gather_kernel(
    const int*   __restrict__ dense_ids,
    const int*   __restrict__ seq_ids,
    const float* __restrict__ tables_dense,
    const float* __restrict__ table_seq,
    const float* __restrict__ inner_w,
    const float* __restrict__ W1)
{
    if (blockIdx.x >= BB / 8) {
        // prep: W1 [1144x30] -> g_W1NK [32x1152] n-major, zero-padded
        int base = (blockIdx.x - BB / 8) * 256 + threadIdx.x;
        for (int e = base; e < 32 * 1152; e += 9 * 256) {
            int n = e / 1152;
            int k = e - n * 1152;
            g_W1NK[e] = (n < HID && k < 1144) ? W1[k * HID + n] : 0.0f;
        }
        return;
    }

    // per-warp reduction scratch: 32 pairs x 33 lanes (stride 33 -> conflict-free)
    __shared__ float Ssc[8 * 32 * 33];

    const int l   = threadIdx.x & 31;
    const int w   = threadIdx.x >> 5;
    const int row = blockIdx.x * 8 + w;

    // ---- dense gather (random, DRAM; 15 independent loads in flight) ----
    ull e[16];
    const ull* td = (const ull*)tables_dense;      // f2 view: 32 per embedding
    const int* dr = dense_ids + row * ND;
    #pragma unroll
    for (int f = 0; f < ND; f++) {
        int id = __ldg(dr + f);
        e[f] = __ldg(td + ((size_t)f * VV + (size_t)id) * 32 + l);
    }

    // ---- sequence mean (L2-resident table), dual accumulators ----
    const int* sr = seq_ids + row * SL;
    const ull* ts = (const ull*)table_seq;
    ull acc0 = 0, acc1 = 0;
    #pragma unroll 5
    for (int s = 0; s < SL; s += 2) {
        int id0 = __ldg(sr + s);
        int id1 = __ldg(sr + s + 1);
        acc0 = f2_add(acc0, __ldg(ts + (size_t)id0 * 32 + l));
        acc1 = f2_add(acc1, __ldg(ts + (size_t)id1 * 32 + l));
    }
    e[15] = f2_mul(f2_add(acc0, acc1), f2_pack(1.0f / 50.0f, 1.0f / 50.0f));

    // ---- write features to global X row (coalesced STG.64) ----
    {
        ull* Xg = (ull*)(g_X + (size_t)row * 1152);
        #pragma unroll
        for (int f = 0; f < 16; f++) Xg[f * 32 + l] = e[f];
        if (l < 8) g_X[(size_t)row * 1152 + 1144 + l] = 0.0f;
    }

    // ---- pairwise from registers; 32-pair chunks via smem transpose reduce ----
    float* sw = Ssc + w * (32 * 33);
    const ull* iw = (const ull*)inner_w;           // f2 view: 32 per pair
    float* lpout = g_X + (size_t)row * 1152 + 1024;

    int p = 0;
    #pragma unroll
    for (int a = 0; a < 15; a++) {
        #pragma unroll
        for (int b = a + 1; b < 16; b++) {
            ull t = f2_mul(f2_mul(e[a], e[b]), __ldg(iw + p * 32 + l));
            sw[(p & 31) * 33 + l] = f2_hadd(t);
            p++;
            if ((p & 31) == 0) {                   // chunk of 32 pairs complete
                __syncwarp();
                const float* rp = sw + l * 33;     // lane l reduces pair (p-32)+l
                float ssum = 0.0f;
                #pragma unroll
                for (int j = 0; j < 32; j++) ssum += rp[j];
                lpout[(p - 32) + l] = ssum;
                __syncwarp();
            }
        }
    }
    // tail chunk: pairs 96..119 (24 pairs)
    __syncwarp();
    if (l < 24) {
        const float* rp = sw + l * 33;
        float ssum = 0.0f;
        #pragma unroll
        for (int j = 0; j < 32; j++) ssum += rp[j];
        lpout[96 + l] = ssum;
    }
}

// ---------------- K2: split-K GEMM. block = 64 rows x 32 cols x 144 k ----------------
__global__ __launch_bounds__(128) void mlp_kernel()
{
    __shared__ float Xsh[64 * TSTR];
    __shared__ float Wsh[32 * TSTR];

    const int t    = threadIdx.x;
    const int spl  = blockIdx.x & 7;
    const int tile = blockIdx.x >> 3;
    const int row0 = tile * 64;
    const int k0s  = spl * KSPL;

    const int cc = t & 7;          // cols cc + 8h, h = 0..3
    const int rr = t >> 3;         // rows 4rr .. 4rr+3

    ull acc[4][4];
    #pragma unroll
    for (int i = 0; i < 4; i++)
        #pragma unroll
        for (int h = 0; h < 4; h++) acc[i][h] = 0;

    for (int c = 0; c < KSPL / KC; c++) {
        const int k0 = k0s + c * KC;
        // stage X: 64 rows x 48 k
        {
            int m  = t >> 1;
            int kk = (t & 1) * 24;
            const float4* src = (const float4*)(g_X + (size_t)(row0 + m) * 1152 + k0 + kk);
            float4* dst = (float4*)(Xsh + m * TSTR + kk);
            #pragma unroll
            for (int j = 0; j < 6; j++) dst[j] = __ldg(src + j);
        }
        // stage W: 32 n x 48 k
        {
            int n  = t >> 2;
            int kk = (t & 3) * 12;
            const float4* src = (const float4*)(g_W1NK + n * 1152 + k0 + kk);
            float4* dst = (float4*)(Wsh + n * TSTR + kk);
            #pragma unroll
            for (int j = 0; j < 3; j++) dst[j] = __ldg(src + j);
        }
        __syncthreads();

        #pragma unroll
        for (int k4 = 0; k4 < KC / 4; k4++) {
            ulonglong2 wv[4];
            #pragma unroll
            for (int h = 0; h < 4; h++)
                wv[h] = *(const ulonglong2*)(Wsh + (cc + 8 * h) * TSTR + k4 * 4);
            #pragma unroll
            for (int i = 0; i < 4; i++) {
                ulonglong2 x = *(const ulonglong2*)(Xsh + (4 * rr + i) * TSTR + k4 * 4);
                #pragma unroll
                for (int h = 0; h < 4; h++) {
                    f2_fma(acc[i][h], x.x, wv[h].x);
                    f2_fma(acc[i][h], x.y, wv[h].y);
                }
            }
        }
        __syncthreads();
    }

    float* P = g_P + ((size_t)spl * BB + row0) * 32;
    #pragma unroll
    for (int i = 0; i < 4; i++)
        #pragma unroll
        for (int h = 0; h < 4; h++)
            P[(4 * rr + i) * 32 + cc + 8 * h] = f2_hadd(acc[i][h]);
}

// ---------------- K3: head — reduce splits, relu, W2, sigmoid ----------------
__global__ __launch_bounds__(256) void head_kernel(
    const float* __restrict__ b1,
    const float* __restrict__ W2,
    const float* __restrict__ b2,
    float*       __restrict__ out)
{
    const int row = blockIdx.x * 256 + threadIdx.x;
    float4 h[8];
    #pragma unroll
    for (int j = 0; j < 8; j++) h[j] = make_float4(0.f, 0.f, 0.f, 0.f);
    #pragma unroll
    for (int s = 0; s < NSPLIT; s++) {
        const float4* P = (const float4*)(g_P + ((size_t)s * BB + row) * 32);
        #pragma unroll
        for (int j = 0; j < 8; j++) {
            float4 v = __ldg(P + j);
            h[j].x += v.x; h[j].y += v.y; h[j].z += v.z; h[j].w += v.w;
        }
    }
    const float* hf = (const float*)h;
    float z = 0.f;
    #pragma unroll
    for (int n = 0; n < HID; n++)
        z += fmaxf(hf[n] + __ldg(b1 + n), 0.f) * __ldg(W2 + n);
    z += __ldg(b2);
    out[row] = 1.0f / (1.0f + expf(-z));
}

extern "C" void kernel_launch(void* const* d_in, const int* in_sizes, int n_in,
                              void* d_out, int out_size) {
    const int*   dense_ids    = (const int*)  d_in[0];
    const int*   seq_ids      = (const int*)  d_in[1];
    const float* tables_dense = (const float*)d_in[2];
    const float* table_seq    = (const float*)d_in[3];
    const float* inner_w      = (const float*)d_in[4];
    const float* W1           = (const float*)d_in[5];
    const float* b1           = (const float*)d_in[6];
    const float* W2           = (const float*)d_in[7];
    const float* b2           = (const float*)d_in[8];
    float* out = (float*)d_out;
    (void)in_sizes; (void)n_in; (void)out_size;

    gather_kernel<<<BB / 8 + 9, 256>>>(dense_ids, seq_ids, tables_dense,
                                       table_seq, inner_w, W1);
    mlp_kernel<<<(BB / 64) * NSPLIT, 128>>>();
    head_kernel<<<BB / 256, 256>>>(b1, W2, b2, out);
}

// round 11
// speedup vs baseline: 1.3237x; 1.0637x over previous
#include <cuda_runtime.h>
#include <math.h>

typedef unsigned long long ull;

#define BB   8192
#define VV   100000
#define ND   15
#define SL   50
#define HID  30
#define NSPLIT 8
#define KSPL 144            /* k per split: 8*144 = 1152 */
#define KC   48             /* k per smem stage */
#define TSTR 52             /* smem tile stride (208 B) */

// X scratch: [row][0..1023 features | 1024..1143 lp | 1144..1151 zero]
__device__ float g_X[(size_t)BB * 1152];
// W1 n-major: g_W1NK[n][k], n<32 (rows 30,31 zero), k<1152 (tail zero)
__device__ float g_W1NK[32 * 1152];
// split-K partials: [split][row][n(32)]
__device__ float g_P[NSPLIT * BB * 32];

// ---------------- f32x2 helpers ----------------
__device__ __forceinline__ ull f2_pack(float x, float y) {
    ull r; asm("mov.b64 %0, {%1, %2};" : "=l"(r) : "f"(x), "f"(y)); return r;
}
__device__ __forceinline__ ull f2_mul(ull a, ull b) {
    ull r; asm("mul.rn.f32x2 %0, %1, %2;" : "=l"(r) : "l"(a), "l"(b)); return r;
}
__device__ __forceinline__ ull f2_add(ull a, ull b) {
    ull r; asm("add.rn.f32x2 %0, %1, %2;" : "=l"(r) : "l"(a), "l"(b)); return r;
}
__device__ __forceinline__ void f2_fma(ull& d, ull a, ull b) {
    asm("fma.rn.f32x2 %0, %1, %2, %0;" : "+l"(d) : "l"(a), "l"(b));
}
__device__ __forceinline__ float f2_hadd(ull a) {
    float lo, hi; asm("mov.b64 {%0, %1}, %2;" : "=f"(lo), "=f"(hi) : "l"(a));
    return lo + hi;
}

// ---------------- K1: gather + register pairwise (smem-transpose reduce) ----------------
__global__ __launch_bounds__(256, 4) void gather_kernel(
    const int*   __restrict__ dense_ids,
    const int*   __restrict__ seq_ids,
    const float* __restrict__ tables_dense,
    const float* __restrict__ table_seq,
    const float* __restrict__ inner_w,
    const float* __restrict__ W1)
{
    if (blockIdx.x >= BB / 8) {
        // prep: W1 [1144x30] -> g_W1NK [32x1152] n-major, zero-padded
        int base = (blockIdx.x - BB / 8) * 256 + threadIdx.x;
        for (int e = base; e < 32 * 1152; e += 9 * 256) {
            int n = e / 1152;
            int k = e - n * 1152;
            g_W1NK[e] = (n < HID && k < 1144) ? W1[k * HID + n] : 0.0f;
        }
        return;
    }

    // per-warp reduction scratch: 32 pairs x 33 lanes (stride 33 -> conflict-free)
    __shared__ float Ssc[8 * 32 * 33];

    const int l   = threadIdx.x & 31;
    const int w   = threadIdx.x >> 5;
    const int row = blockIdx.x * 8 + w;

    // ---- dense gather (random, DRAM; 15 independent loads in flight) ----
    ull e[16];
    const ull* td = (const ull*)tables_dense;      // f2 view: 32 per embedding
    const int* dr = dense_ids + row * ND;
    #pragma unroll
    for (int f = 0; f < ND; f++) {
        int id = __ldg(dr + f);
        e[f] = __ldg(td + ((size_t)f * VV + (size_t)id) * 32 + l);
    }

    // ---- sequence mean (L2-resident table), dual accumulators ----
    const int* sr = seq_ids + row * SL;
    const ull* ts = (const ull*)table_seq;
    ull acc0 = 0, acc1 = 0;
    #pragma unroll 5
    for (int s = 0; s < SL; s += 2) {
        int id0 = __ldg(sr + s);
        int id1 = __ldg(sr + s + 1);
        acc0 = f2_add(acc0, __ldg(ts + (size_t)id0 * 32 + l));
        acc1 = f2_add(acc1, __ldg(ts + (size_t)id1 * 32 + l));
    }
    e[15] = f2_mul(f2_add(acc0, acc1), f2_pack(1.0f / 50.0f, 1.0f / 50.0f));

    // ---- write features to global X row (coalesced STG.64) ----
    {
        ull* Xg = (ull*)(g_X + (size_t)row * 1152);
        #pragma unroll
        for (int f = 0; f < 16; f++) Xg[f * 32 + l] = e[f];
        if (l < 8) g_X[(size_t)row * 1152 + 1144 + l] = 0.0f;
    }

    // ---- pairwise from registers; 32-pair chunks via smem transpose reduce ----
    float* sw = Ssc + w * (32 * 33);
    const ull* iw = (const ull*)inner_w;           // f2 view: 32 per pair
    float* lpout = g_X + (size_t)row * 1152 + 1024;

    int p = 0;
    #pragma unroll
    for (int a = 0; a < 15; a++) {
        #pragma unroll
        for (int b = a + 1; b < 16; b++) {
            ull t = f2_mul(f2_mul(e[a], e[b]), __ldg(iw + p * 32 + l));
            sw[(p & 31) * 33 + l] = f2_hadd(t);
            p++;
            if ((p & 31) == 0) {                   // chunk of 32 pairs complete
                __syncwarp();
                const float* rp = sw + l * 33;     // lane l reduces pair (p-32)+l
                float ssum = 0.0f;
                #pragma unroll
                for (int j = 0; j < 32; j++) ssum += rp[j];
                lpout[(p - 32) + l] = ssum;
                __syncwarp();
            }
        }
    }
    // tail chunk: pairs 96..119 (24 pairs)
    __syncwarp();
    if (l < 24) {
        const float* rp = sw + l * 33;
        float ssum = 0.0f;
        #pragma unroll
        for (int j = 0; j < 32; j++) ssum += rp[j];
        lpout[96 + l] = ssum;
    }
}

// ---------------- K2: split-K GEMM, double-buffered. 64 rows x 32 cols x 144 k ----------------
__global__ __launch_bounds__(128) void mlp_kernel()
{
    __shared__ float Xsh[2][64 * TSTR];
    __shared__ float Wsh[2][32 * TSTR];

    const int t    = threadIdx.x;
    const int spl  = blockIdx.x & 7;
    const int row0 = (blockIdx.x >> 3) * 64;
    const int k0s  = spl * KSPL;

    const int cc = t & 7;          // cols cc + 8h, h = 0..3
    const int rr = t >> 3;         // rows 4rr .. 4rr+3

    // staging assignment (float4 units; stage stride = KC/4 = 12)
    const int xm = t >> 1, xk = (t & 1) * 24;
    const int wn = t >> 2, wk = (t & 3) * 12;
    const float4* xsrc = (const float4*)(g_X + (size_t)(row0 + xm) * 1152 + k0s + xk);
    const float4* wsrc = (const float4*)(g_W1NK + wn * 1152 + k0s + wk);

    float4 xr[6], wr[3];
    #pragma unroll
    for (int j = 0; j < 6; j++) xr[j] = __ldg(xsrc + j);
    #pragma unroll
    for (int j = 0; j < 3; j++) wr[j] = __ldg(wsrc + j);
    #pragma unroll
    for (int j = 0; j < 6; j++) *(float4*)(Xsh[0] + xm * TSTR + xk + j * 4) = xr[j];
    #pragma unroll
    for (int j = 0; j < 3; j++) *(float4*)(Wsh[0] + wn * TSTR + wk + j * 4) = wr[j];
    __syncthreads();

    ull acc[4][4];
    #pragma unroll
    for (int i = 0; i < 4; i++)
        #pragma unroll
        for (int h = 0; h < 4; h++) acc[i][h] = 0;

    #pragma unroll
    for (int c = 0; c < 3; c++) {
        // prefetch next stage into registers (hidden under compute)
        if (c < 2) {
            #pragma unroll
            for (int j = 0; j < 6; j++) xr[j] = __ldg(xsrc + (c + 1) * 12 + j);
            #pragma unroll
            for (int j = 0; j < 3; j++) wr[j] = __ldg(wsrc + (c + 1) * 12 + j);
        }
        const float* Xb = Xsh[c & 1];
        const float* Wb = Wsh[c & 1];
        #pragma unroll
        for (int k4 = 0; k4 < KC / 4; k4++) {
            ulonglong2 wv[4];
            #pragma unroll
            for (int h = 0; h < 4; h++)
                wv[h] = *(const ulonglong2*)(Wb + (cc + 8 * h) * TSTR + k4 * 4);
            #pragma unroll
            for (int i = 0; i < 4; i++) {
                ulonglong2 x = *(const ulonglong2*)(Xb + (4 * rr + i) * TSTR + k4 * 4);
                #pragma unroll
                for (int h = 0; h < 4; h++) {
                    f2_fma(acc[i][h], x.x, wv[h].x);
                    f2_fma(acc[i][h], x.y, wv[h].y);
                }
            }
        }
        if (c < 2) {
            const int nb = (c + 1) & 1;
            #pragma unroll
            for (int j = 0; j < 6; j++) *(float4*)(Xsh[nb] + xm * TSTR + xk + j * 4) = xr[j];
            #pragma unroll
            for (int j = 0; j < 3; j++) *(float4*)(Wsh[nb] + wn * TSTR + wk + j * 4) = wr[j];
            __syncthreads();
        }
    }

    // write partials (deterministic)
    float* P = g_P + ((size_t)spl * BB + row0) * 32;
    #pragma unroll
    for (int i = 0; i < 4; i++)
        #pragma unroll
        for (int h = 0; h < 4; h++)
            P[(4 * rr + i) * 32 + cc + 8 * h] = f2_hadd(acc[i][h]);
}

// ---------------- K3: head — reduce splits, relu, W2, sigmoid ----------------
__global__ __launch_bounds__(256) void head_kernel(
    const float* __restrict__ b1,
    const float* __restrict__ W2,
    const float* __restrict__ b2,
    float*       __restrict__ out)
{
    const int row = blockIdx.x * 256 + threadIdx.x;
    float4 h[8];
    #pragma unroll
    for (int j = 0; j < 8; j++) h[j] = make_float4(0.f, 0.f, 0.f, 0.f);
    #pragma unroll
    for (int s = 0; s < NSPLIT; s++) {
        const float4* P = (const float4*)(g_P + ((size_t)s * BB + row) * 32);
        #pragma unroll
        for (int j = 0; j < 8; j++) {
            float4 v = __ldg(P + j);
            h[j].x += v.x; h[j].y += v.y; h[j].z += v.z; h[j].w += v.w;
        }
    }
    const float* hf = (const float*)h;
    float z = 0.f;
    #pragma unroll
    for (int n = 0; n < HID; n++)
        z += fmaxf(hf[n] + __ldg(b1 + n), 0.f) * __ldg(W2 + n);
    z += __ldg(b2);
    out[row] = 1.0f / (1.0f + expf(-z));
}

extern "C" void kernel_launch(void* const* d_in, const int* in_sizes, int n_in,
                              void* d_out, int out_size) {
    const int*   dense_ids    = (const int*)  d_in[0];
    const int*   seq_ids      = (const int*)  d_in[1];
    const float* tables_dense = (const float*)d_in[2];
    const float* table_seq    = (const float*)d_in[3];
    const float* inner_w      = (const float*)d_in[4];
    const float* W1           = (const float*)d_in[5];
    const float* b1           = (const float*)d_in[6];
    const float* W2           = (const float*)d_in[7];
    const float* b2           = (const float*)d_in[8];
    float* out = (float*)d_out;
    (void)in_sizes; (void)n_in; (void)out_size;

    gather_kernel<<<BB / 8 + 9, 256>>>(dense_ids, seq_ids, tables_dense,
                                       table_seq, inner_w, W1);
    mlp_kernel<<<(BB / 64) * NSPLIT, 128>>>();
    head_kernel<<<BB / 256, 256>>>(b1, W2, b2, out);
}

// round 13
// speedup vs baseline: 1.4309x; 1.0810x over previous
#include <cuda_runtime.h>
#include <stdint.h>
#include <math.h>

typedef unsigned long long ull;

#define BB   8192
#define VV   100000
#define ND   15
#define SL   50
#define HID  30
#define NSPLIT 8
#define KSPL 144            /* k per split: 8*144 = 1152 */
#define KC   48             /* k per smem stage */
#define TSTR 52             /* smem tile stride in floats (208 B) */

// X scratch: [row][0..1023 features | 1024..1143 lp | 1144..1151 zero]
__device__ float g_X[(size_t)BB * 1152];
// W1 n-major: g_W1NK[n][k], n<32 (rows 30,31 zero), k<1152 (tail zero)
__device__ float g_W1NK[32 * 1152];
// split-K partials: [split][row][n(32)]
__device__ float g_P[NSPLIT * BB * 32];

// ---------------- f32x2 helpers ----------------
__device__ __forceinline__ ull f2_pack(float x, float y) {
    ull r; asm("mov.b64 %0, {%1, %2};" : "=l"(r) : "f"(x), "f"(y)); return r;
}
__device__ __forceinline__ ull f2_mul(ull a, ull b) {
    ull r; asm("mul.rn.f32x2 %0, %1, %2;" : "=l"(r) : "l"(a), "l"(b)); return r;
}
__device__ __forceinline__ ull f2_add(ull a, ull b) {
    ull r; asm("add.rn.f32x2 %0, %1, %2;" : "=l"(r) : "l"(a), "l"(b)); return r;
}
__device__ __forceinline__ void f2_fma(ull& d, ull a, ull b) {
    asm("fma.rn.f32x2 %0, %1, %2, %0;" : "+l"(d) : "l"(a), "l"(b));
}
__device__ __forceinline__ float f2_hadd(ull a) {
    float lo, hi; asm("mov.b64 {%0, %1}, %2;" : "=f"(lo), "=f"(hi) : "l"(a));
    return lo + hi;
}
__device__ __forceinline__ void cp16(unsigned dst_smem, const void* src) {
    asm volatile("cp.async.cg.shared.global [%0], [%1], 16;"
                 :: "r"(dst_smem), "l"(src));
}
__device__ __forceinline__ unsigned smem_u32(const void* p) {
    return (unsigned)__cvta_generic_to_shared(p);
}

// ---------------- K1: gather + register pairwise (smem-transpose reduce) ----------------
__global__ __launch_bounds__(256, 4) void gather_kernel(
    const int*   __restrict__ dense_ids,
    const int*   __restrict__ seq_ids,
    const float* __restrict__ tables_dense,
    const float* __restrict__ table_seq,
    const float* __restrict__ inner_w,
    const float* __restrict__ W1)
{
    if (blockIdx.x >= BB / 8) {
        // prep: W1 [1144x30] -> g_W1NK [32x1152] n-major, zero-padded
        int base = (blockIdx.x - BB / 8) * 256 + threadIdx.x;
        for (int e = base; e < 32 * 1152; e += 9 * 256) {
            int n = e / 1152;
            int k = e - n * 1152;
            g_W1NK[e] = (n < HID && k < 1144) ? W1[k * HID + n] : 0.0f;
        }
        return;
    }

    // per-warp reduction scratch: 32 pairs x 34-float rows (even stride for ull reads)
    __shared__ float Ssc[8 * 32 * 34];

    const int l   = threadIdx.x & 31;
    const int w   = threadIdx.x >> 5;
    const int row = blockIdx.x * 8 + w;

    // ---- dense gather (random, DRAM; 15 independent loads in flight) ----
    ull e[16];
    const ull* td = (const ull*)tables_dense;      // f2 view: 32 per embedding
    const int* dr = dense_ids + row * ND;
    #pragma unroll
    for (int f = 0; f < ND; f++) {
        int id = __ldg(dr + f);
        e[f] = __ldg(td + ((size_t)f * VV + (size_t)id) * 32 + l);
    }

    // ---- sequence mean (L2-resident table), dual accumulators ----
    const int* sr = seq_ids + row * SL;
    const ull* ts = (const ull*)table_seq;
    ull acc0 = 0, acc1 = 0;
    #pragma unroll 10
    for (int s = 0; s < SL; s += 2) {
        int id0 = __ldg(sr + s);
        int id1 = __ldg(sr + s + 1);
        acc0 = f2_add(acc0, __ldg(ts + (size_t)id0 * 32 + l));
        acc1 = f2_add(acc1, __ldg(ts + (size_t)id1 * 32 + l));
    }
    e[15] = f2_mul(f2_add(acc0, acc1), f2_pack(1.0f / 50.0f, 1.0f / 50.0f));

    // ---- write features to global X row (coalesced STG.64) ----
    {
        ull* Xg = (ull*)(g_X + (size_t)row * 1152);
        #pragma unroll
        for (int f = 0; f < 16; f++) Xg[f * 32 + l] = e[f];
        if (l < 8) g_X[(size_t)row * 1152 + 1144 + l] = 0.0f;
    }

    // ---- pairwise from registers; 32-pair chunks via smem transpose reduce ----
    float* sw = Ssc + w * (32 * 34);
    const ull* iw = (const ull*)inner_w;           // f2 view: 32 per pair
    float* lpout = g_X + (size_t)row * 1152 + 1024;

    int p = 0;
    #pragma unroll
    for (int a = 0; a < 15; a++) {
        #pragma unroll
        for (int b = a + 1; b < 16; b++) {
            ull t = f2_mul(f2_mul(e[a], e[b]), __ldg(iw + p * 32 + l));
            sw[(p & 31) * 34 + l] = f2_hadd(t);
            p++;
            if ((p & 31) == 0) {                   // chunk of 32 pairs complete
                __syncwarp();
                const ull* rp = (const ull*)(sw + l * 34);   // lane l reduces pair (p-32)+l
                ull s2 = 0;
                #pragma unroll
                for (int j = 0; j < 16; j++) s2 = f2_add(s2, rp[j]);
                lpout[(p - 32) + l] = f2_hadd(s2);
                __syncwarp();
            }
        }
    }
    // tail chunk: pairs 96..119 (24 pairs)
    __syncwarp();
    if (l < 24) {
        const ull* rp = (const ull*)(sw + l * 34);
        ull s2 = 0;
        #pragma unroll
        for (int j = 0; j < 16; j++) s2 = f2_add(s2, rp[j]);
        lpout[96 + l] = f2_hadd(s2);
    }
}

// ---------------- K2: split-K GEMM, cp.async double-buffered. 64r x 32c x 144k ----------------
__global__ __launch_bounds__(256) void mlp_kernel()
{
    __shared__ float Xsh[2][64 * TSTR];
    __shared__ float Wsh[2][32 * TSTR];

    const int t    = threadIdx.x;
    const int spl  = blockIdx.x & 7;
    const int row0 = (blockIdx.x >> 3) * 64;
    const int k0s  = spl * KSPL;

    const int cc = t & 15;         // cols cc, cc+16
    const int rt = t >> 4;         // rows 4rt .. 4rt+3

    // staging task assignment (float4 units, KC/4 = 12 per row)
    // X: 768 tasks = 3 per thread;  W: 384 tasks = 1 per thread + 1 for t<128
    int xm[3], xq[3];
    #pragma unroll
    for (int j = 0; j < 3; j++) {
        int task = j * 256 + t;
        xm[j] = task / 12; xq[j] = task - xm[j] * 12;
    }
    int wn0 = t / 12, wq0 = t - wn0 * 12;
    int wn1 = (256 + t) / 12, wq1 = (256 + t) - wn1 * 12;
    const bool w1on = (t < 128);

    // stage (k-offset k0) into buffer b
    auto stage = [&](int b, int k0) {
        #pragma unroll
        for (int j = 0; j < 3; j++) {
            const float* src = g_X + (size_t)(row0 + xm[j]) * 1152 + k0 + xq[j] * 4;
            cp16(smem_u32(&Xsh[b][xm[j] * TSTR + xq[j] * 4]), src);
        }
        {
            const float* src = g_W1NK + wn0 * 1152 + k0 + wq0 * 4;
            cp16(smem_u32(&Wsh[b][wn0 * TSTR + wq0 * 4]), src);
        }
        if (w1on) {
            const float* src = g_W1NK + wn1 * 1152 + k0 + wq1 * 4;
            cp16(smem_u32(&Wsh[b][wn1 * TSTR + wq1 * 4]), src);
        }
        asm volatile("cp.async.commit_group;");
    };

    stage(0, k0s);
    stage(1, k0s + KC);

    ull acc[4][2];
    #pragma unroll
    for (int i = 0; i < 4; i++) { acc[i][0] = 0; acc[i][1] = 0; }

    #pragma unroll
    for (int c = 0; c < 3; c++) {
        if (c < 2) asm volatile("cp.async.wait_group 1;");
        else       asm volatile("cp.async.wait_group 0;");
        __syncthreads();

        const float* Xb = Xsh[c & 1];
        const float* Wb = Wsh[c & 1];
        #pragma unroll
        for (int k4 = 0; k4 < KC / 4; k4++) {
            ulonglong2 w0 = *(const ulonglong2*)(Wb + cc * TSTR + k4 * 4);
            ulonglong2 w1 = *(const ulonglong2*)(Wb + (cc + 16) * TSTR + k4 * 4);
            #pragma unroll
            for (int i = 0; i < 4; i++) {
                ulonglong2 x = *(const ulonglong2*)(Xb + (4 * rt + i) * TSTR + k4 * 4);
                f2_fma(acc[i][0], x.x, w0.x);
                f2_fma(acc[i][0], x.y, w0.y);
                f2_fma(acc[i][1], x.x, w1.x);
                f2_fma(acc[i][1], x.y, w1.y);
            }
        }
        __syncthreads();
        if (c == 0) stage(0, k0s + 2 * KC);   // S2 reuses buf0 (safe: post-compute sync)
    }

    // write partials (deterministic)
    float* P = g_P + ((size_t)spl * BB + row0) * 32;
    #pragma unroll
    for (int i = 0; i < 4; i++) {
        P[(4 * rt + i) * 32 + cc     ] = f2_hadd(acc[i][0]);
        P[(4 * rt + i) * 32 + cc + 16] = f2_hadd(acc[i][1]);
    }
}

// ---------------- K3: head — reduce splits, relu, W2, sigmoid ----------------
__global__ __launch_bounds__(256) void head_kernel(
    const float* __restrict__ b1,
    const float* __restrict__ W2,
    const float* __restrict__ b2,
    float*       __restrict__ out)
{
    const int row = blockIdx.x * 256 + threadIdx.x;
    float4 h[8];
    #pragma unroll
    for (int j = 0; j < 8; j++) h[j] = make_float4(0.f, 0.f, 0.f, 0.f);
    #pragma unroll
    for (int s = 0; s < NSPLIT; s++) {
        const float4* P = (const float4*)(g_P + ((size_t)s * BB + row) * 32);
        #pragma unroll
        for (int j = 0; j < 8; j++) {
            float4 v = __ldg(P + j);
            h[j].x += v.x; h[j].y += v.y; h[j].z += v.z; h[j].w += v.w;
        }
    }
    const float* hf = (const float*)h;
    float z = 0.f;
    #pragma unroll
    for (int n = 0; n < HID; n++)
        z += fmaxf(hf[n] + __ldg(b1 + n), 0.f) * __ldg(W2 + n);
    z += __ldg(b2);
    out[row] = 1.0f / (1.0f + expf(-z));
}

extern "C" void kernel_launch(void* const* d_in, const int* in_sizes, int n_in,
                              void* d_out, int out_size) {
    const int*   dense_ids    = (const int*)  d_in[0];
    const int*   seq_ids      = (const int*)  d_in[1];
    const float* tables_dense = (const float*)d_in[2];
    const float* table_seq    = (const float*)d_in[3];
    const float* inner_w      = (const float*)d_in[4];
    const float* W1           = (const float*)d_in[5];
    const float* b1           = (const float*)d_in[6];
    const float* W2           = (const float*)d_in[7];
    const float* b2           = (const float*)d_in[8];
    float* out = (float*)d_out;
    (void)in_sizes; (void)n_in; (void)out_size;

    gather_kernel<<<BB / 8 + 9, 256>>>(dense_ids, seq_ids, tables_dense,
                                       table_seq, inner_w, W1);
    mlp_kernel<<<(BB / 64) * NSPLIT, 256>>>();
    head_kernel<<<BB / 256, 256>>>(b1, W2, b2, out);
}

// round 16
// speedup vs baseline: 1.4801x; 1.0344x over previous
#include <cuda_runtime.h>
#include <stdint.h>
#include <math.h>

typedef unsigned long long ull;

#define BB   8192
#define VV   100000
#define ND   15
#define SL   50
#define HID  30
#define CH   128            /* k per chunk: 9*128 = 1152 */
#define NCH  9

// X scratch: [row][0..1023 features | 1024..1143 lp | 1144..1151 zero]
__device__ float g_X[(size_t)BB * 1152];
// W1 n-major: g_W1NK[n][k], n<32 (rows 30,31 zero), k<1152 (tail zero)
__device__ float g_W1NK[32 * 1152];
// layer-1 outputs: [row][n(32)]
__device__ float g_H[(size_t)BB * 32];

// ---------------- f32x2 helpers ----------------
__device__ __forceinline__ ull f2_pack(float x, float y) {
    ull r; asm("mov.b64 %0, {%1, %2};" : "=l"(r) : "f"(x), "f"(y)); return r;
}
__device__ __forceinline__ ull f2_mul(ull a, ull b) {
    ull r; asm("mul.rn.f32x2 %0, %1, %2;" : "=l"(r) : "l"(a), "l"(b)); return r;
}
__device__ __forceinline__ ull f2_add(ull a, ull b) {
    ull r; asm("add.rn.f32x2 %0, %1, %2;" : "=l"(r) : "l"(a), "l"(b)); return r;
}
__device__ __forceinline__ void f2_fma(ull& d, ull a, ull b) {
    asm("fma.rn.f32x2 %0, %1, %2, %0;" : "+l"(d) : "l"(a), "l"(b));
}
__device__ __forceinline__ float f2_hadd(ull a) {
    float lo, hi; asm("mov.b64 {%0, %1}, %2;" : "=f"(lo), "=f"(hi) : "l"(a));
    return lo + hi;
}
__device__ __forceinline__ void cp16(unsigned dst_smem, const void* src) {
    asm volatile("cp.async.cg.shared.global [%0], [%1], 16;"
                 :: "r"(dst_smem), "l"(src));
}
__device__ __forceinline__ unsigned smem_u32(const void* p) {
    return (unsigned)__cvta_generic_to_shared(p);
}

// ---------------- K1: gather + register pairwise (smem-transpose reduce) ----------------
__global__ __launch_bounds__(256, 4) void gather_kernel(
    const int*   __restrict__ dense_ids,
    const int*   __restrict__ seq_ids,
    const float* __restrict__ tables_dense,
    const float* __restrict__ table_seq,
    const float* __restrict__ inner_w,
    const float* __restrict__ W1)
{
    if (blockIdx.x >= BB / 8) {
        // prep: W1 [1144x30] -> g_W1NK [32x1152] n-major, zero-padded
        int base = (blockIdx.x - BB / 8) * 256 + threadIdx.x;
        for (int e = base; e < 32 * 1152; e += 9 * 256) {
            int n = e / 1152;
            int k = e - n * 1152;
            g_W1NK[e] = (n < HID && k < 1144) ? W1[k * HID + n] : 0.0f;
        }
        return;
    }

    // per-warp reduction scratch: 32 pairs x 33-float rows (stride 33 -> conflict-free)
    __shared__ float Ssc[8 * 32 * 33];

    const int l   = threadIdx.x & 31;
    const int w   = threadIdx.x >> 5;
    const int row = blockIdx.x * 8 + w;

    // ---- dense gather (random, DRAM; 15 independent loads in flight) ----
    ull e[16];
    const ull* td = (const ull*)tables_dense;      // f2 view: 32 per embedding
    const int* dr = dense_ids + row * ND;
    #pragma unroll
    for (int f = 0; f < ND; f++) {
        int id = __ldg(dr + f);
        e[f] = __ldg(td + ((size_t)f * VV + (size_t)id) * 32 + l);
    }

    // ---- sequence mean (L2-resident table), dual accumulators ----
    const int* sr = seq_ids + row * SL;
    const ull* ts = (const ull*)table_seq;
    ull acc0 = 0, acc1 = 0;
    #pragma unroll 10
    for (int s = 0; s < SL; s += 2) {
        int id0 = __ldg(sr + s);
        int id1 = __ldg(sr + s + 1);
        acc0 = f2_add(acc0, __ldg(ts + (size_t)id0 * 32 + l));
        acc1 = f2_add(acc1, __ldg(ts + (size_t)id1 * 32 + l));
    }
    e[15] = f2_mul(f2_add(acc0, acc1), f2_pack(1.0f / 50.0f, 1.0f / 50.0f));

    // ---- write features to global X row (coalesced STG.64) ----
    {
        ull* Xg = (ull*)(g_X + (size_t)row * 1152);
        #pragma unroll
        for (int f = 0; f < 16; f++) Xg[f * 32 + l] = e[f];
        if (l < 8) g_X[(size_t)row * 1152 + 1144 + l] = 0.0f;
    }

    // ---- pairwise from registers; 32-pair chunks via smem transpose reduce ----
    float* sw = Ssc + w * (32 * 33);
    const ull* iw = (const ull*)inner_w;           // f2 view: 32 per pair
    float* lpout = g_X + (size_t)row * 1152 + 1024;

    int p = 0;
    #pragma unroll
    for (int a = 0; a < 15; a++) {
        #pragma unroll
        for (int b = a + 1; b < 16; b++) {
            ull t = f2_mul(f2_mul(e[a], e[b]), __ldg(iw + p * 32 + l));
            sw[(p & 31) * 33 + l] = f2_hadd(t);
            p++;
            if ((p & 31) == 0) {                   // chunk of 32 pairs complete
                __syncwarp();
                const float* rp = sw + l * 33;     // lane l reduces pair (p-32)+l
                float ssum = 0.0f;
                #pragma unroll
                for (int j = 0; j < 32; j++) ssum += rp[j];
                lpout[(p - 32) + l] = ssum;
                __syncwarp();
            }
        }
    }
    // tail chunk: pairs 96..119 (24 pairs)
    __syncwarp();
    if (l < 24) {
        const float* rp = sw + l * 33;
        float ssum = 0.0f;
        #pragma unroll
        for (int j = 0; j < 32; j++) ssum += rp[j];
        lpout[96 + l] = ssum;
    }
}

// ---------------- K2: GEMM, k-distributed lanes. block = 16 rows x 16 cols x full-K ----------------
__global__ __launch_bounds__(256) void mlp_kernel()
{
    __shared__ float Xsh[2][16 * CH];
    __shared__ float Wsh[2][16 * CH];

    const int t    = threadIdx.x;
    const int l    = t & 31;
    const int w    = t >> 5;
    const int row0 = (blockIdx.x >> 1) * 16;
    const int colh = (blockIdx.x & 1) * 16;

    const int rg = (w & 1) * 8;    // warp row group: rows rg..rg+7 (within 16)
    const int cg = (w >> 1) * 4;   // warp col group: cols cg..cg+3 (within 16)

    // staging: 1024 float4 tasks (X: 0..511, W: 512..1023), 4 per thread
    auto stage = [&](int b, int c) {
        #pragma unroll
        for (int j = 0; j < 4; j++) {
            int task = j * 256 + t;
            if (task < 512) {
                int r = task >> 5, q = task & 31;
                const float* src = g_X + (size_t)(row0 + r) * 1152 + c * CH + q * 4;
                cp16(smem_u32(&Xsh[b][r * CH + q * 4]), src);
            } else {
                int tw = task - 512;
                int n = tw >> 5, q = tw & 31;
                const float* src = g_W1NK + (colh + n) * 1152 + c * CH + q * 4;
                cp16(smem_u32(&Wsh[b][n * CH + q * 4]), src);
            }
        }
        asm volatile("cp.async.commit_group;");
    };

    stage(0, 0);
    stage(1, 1);

    ull acc[8][4];
    #pragma unroll
    for (int r = 0; r < 8; r++)
        #pragma unroll
        for (int cc = 0; cc < 4; cc++) acc[r][cc] = 0;

    for (int c = 0; c < NCH; c++) {
        if (c < NCH - 1) asm volatile("cp.async.wait_group 1;");
        else             asm volatile("cp.async.wait_group 0;");
        __syncthreads();

        const float* Xb = Xsh[c & 1];
        const float* Wb = Wsh[c & 1];

        ulonglong2 wv[4];
        #pragma unroll
        for (int cc = 0; cc < 4; cc++)
            wv[cc] = *(const ulonglong2*)(Wb + (cg + cc) * CH + 4 * l);
        #pragma unroll
        for (int r = 0; r < 8; r++) {
            ulonglong2 x = *(const ulonglong2*)(Xb + (rg + r) * CH + 4 * l);
            #pragma unroll
            for (int cc = 0; cc < 4; cc++) {
                f2_fma(acc[r][cc], x.x, wv[cc].x);
                f2_fma(acc[r][cc], x.y, wv[cc].y);
            }
        }
        __syncthreads();
        if (c < NCH - 2) stage(c & 1, c + 2);   // reuses just-consumed buffer
    }

    // cross-lane k-reduction: 32 butterflies, lane (r*4+cc) keeps value
    float res = 0.0f;
    #pragma unroll
    for (int r = 0; r < 8; r++) {
        #pragma unroll
        for (int cc = 0; cc < 4; cc++) {
            float s = f2_hadd(acc[r][cc]);
            s += __shfl_xor_sync(0xffffffffu, s, 16);
            s += __shfl_xor_sync(0xffffffffu, s, 8);
            s += __shfl_xor_sync(0xffffffffu, s, 4);
            s += __shfl_xor_sync(0xffffffffu, s, 2);
            s += __shfl_xor_sync(0xffffffffu, s, 1);
            if (l == r * 4 + cc) res = s;
        }
    }
    // lane l owns cell (r = l>>2, cc = l&3)
    g_H[(size_t)(row0 + rg + (l >> 2)) * 32 + colh + cg + (l & 3)] = res;
}

// ---------------- K3: head — relu, W2, sigmoid ----------------
__global__ __launch_bounds__(256) void head_kernel(
    const float* __restrict__ b1,
    const float* __restrict__ W2,
    const float* __restrict__ b2,
    float*       __restrict__ out)
{
    const int row = blockIdx.x * 256 + threadIdx.x;
    float4 h[8];
    const float4* H = (const float4*)(g_H + (size_t)row * 32);
    #pragma unroll
    for (int j = 0; j < 8; j++) h[j] = __ldg(H + j);
    const float* hf = (const float*)h;
    float z = 0.f;
    #pragma unroll
    for (int n = 0; n < HID; n++)
        z += fmaxf(hf[n] + __ldg(b1 + n), 0.f) * __ldg(W2 + n);
    z += __ldg(b2);
    out[row] = 1.0f / (1.0f + expf(-z));
}

extern "C" void kernel_launch(void* const* d_in, const int* in_sizes, int n_in,
                              void* d_out, int out_size) {
    const int*   dense_ids    = (const int*)  d_in[0];
    const int*   seq_ids      = (const int*)  d_in[1];
    const float* tables_dense = (const float*)d_in[2];
    const float* table_seq    = (const float*)d_in[3];
    const float* inner_w      = (const float*)d_in[4];
    const float* W1           = (const float*)d_in[5];
    const float* b1           = (const float*)d_in[6];
    const float* W2           = (const float*)d_in[7];
    const float* b2           = (const float*)d_in[8];
    float* out = (float*)d_out;
    (void)in_sizes; (void)n_in; (void)out_size;

    gather_kernel<<<BB / 8 + 9, 256>>>(dense_ids, seq_ids, tables_dense,
                                       table_seq, inner_w, W1);
    mlp_kernel<<<(BB / 16) * 2, 256>>>();
    head_kernel<<<BB / 256, 256>>>(b1, W2, b2, out);
}